// round 2
// baseline (speedup 1.0000x reference)
#include <cuda_runtime.h>
#include <cstdint>

// ---------------------------------------------------------------------------
// SepConvLayer: 64-deep sequential 3x3 conv+ReLU6 chain, then per-pixel
// 64x64 matvec + BN + ReLU6 + 64->1 reduction.
//
// Kernel A: fused chain via halo recomputation (halo=64), one launch.
// Kernel B: phase-2 GEMM in packed f32x2.
// ---------------------------------------------------------------------------

#define BUF  192          // 64 interior + 2*64 halo
#define BSTR 193          // padded row stride (odd -> no bank conflicts)
#define NPIX (8 * 256 * 256)

// scratch: ys[c][b][h][w], 64 * 524288 floats = 134 MB
__device__ float g_ys[64ull * NPIX];

typedef unsigned long long u64;

__device__ __forceinline__ u64 f2fma(u64 a, u64 b, u64 c) {
    u64 d;
    asm("fma.rn.f32x2 %0, %1, %2, %3;" : "=l"(d) : "l"(a), "l"(b), "l"(c));
    return d;
}
__device__ __forceinline__ u64 f2pack(float x, float y) {
    u64 r; asm("mov.b64 %0, {%1, %2};" : "=l"(r) : "f"(x), "f"(y)); return r;
}
__device__ __forceinline__ void f2unpack(u64 v, float& x, float& y) {
    asm("mov.b64 {%0, %1}, %2;" : "=f"(x), "=f"(y) : "l"(v));
}

// ---------------------------------------------------------------------------
// Kernel A: the conv chain. Grid (4,4,8), 512 threads, ~147 KB dyn smem.
// ---------------------------------------------------------------------------
__global__ void __launch_bounds__(512) chain_kernel(const float* __restrict__ x,
                                                    const float* __restrict__ dw) {
    extern __shared__ float sm[];
    float* buf = sm;                  // BUF*BSTR floats
    float* wsh = sm + BUF * BSTR;     // 576 floats (all stage weights)

    const int b   = blockIdx.z;
    const int gy0 = (int)blockIdx.y * 64 - 64;
    const int gx0 = (int)blockIdx.x * 64 - 64;
    const float* __restrict__ xin = x + (size_t)b * 64 * 65536;  // x[b][0]

    for (int i = threadIdx.x; i < 576; i += 512) wsh[i] = dw[i];

    // initial 192x192 load, zero-filled outside the image (SAME padding)
    for (int idx = threadIdx.x; idx < BUF * BUF; idx += 512) {
        int i = idx / BUF, j = idx - i * BUF;
        int gy = gy0 + i, gx = gx0 + j;
        float v = 0.f;
        if ((unsigned)gy < 256u && (unsigned)gx < 256u)
            v = __ldg(xin + gy * 256 + gx);
        buf[i * BSTR + j] = v;
    }
    __syncthreads();

    const int txt = threadIdx.x & 63;   // column lane 0..63
    const int tyt = threadIdx.x >> 6;   // row band 0..7

    for (int s = 0; s < 64; ++s) {
        const float w0 = wsh[s * 9 + 0], w1 = wsh[s * 9 + 1], w2 = wsh[s * 9 + 2];
        const float w3 = wsh[s * 9 + 3], w4 = wsh[s * 9 + 4], w5 = wsh[s * 9 + 5];
        const float w6 = wsh[s * 9 + 6], w7 = wsh[s * 9 + 7], w8 = wsh[s * 9 + 8];

        const int o   = s + 1;          // output region origin
        const int L   = 190 - 2 * s;    // output region side (190..64)
        const int rpb = (L + 7) >> 3;   // rows per band (<=24)
        const int rbase = tyt * rpb;
        const int r0    = o + rbase;

        float out[3][24];

        // ---- compute all outputs into registers (reads only) ----
        #pragma unroll
        for (int k = 0; k < 3; ++k) {
            const int cj = txt + 64 * k;
            const int j  = o + cj;
            if (cj < L && rbase < L) {
                // prime 3x3 vertical sliding window at rows r0-1, r0
                float a0 = buf[(r0 - 1) * BSTR + j - 1];
                float a1 = buf[(r0 - 1) * BSTR + j    ];
                float a2 = buf[(r0 - 1) * BSTR + j + 1];
                float b0 = buf[ r0      * BSTR + j - 1];
                float b1 = buf[ r0      * BSTR + j    ];
                float b2 = buf[ r0      * BSTR + j + 1];
                const int  gx   = gx0 + j;
                const bool gxok = (unsigned)gx < 256u;
                #pragma unroll
                for (int r = 0; r < 24; ++r) {
                    if (rbase + r < L) {
                        const int i = r0 + r;
                        float c0 = buf[(i + 1) * BSTR + j - 1];
                        float c1 = buf[(i + 1) * BSTR + j    ];
                        float c2 = buf[(i + 1) * BSTR + j + 1];
                        float v = w0 * a0;
                        v = fmaf(w1, a1, v); v = fmaf(w2, a2, v);
                        v = fmaf(w3, b0, v); v = fmaf(w4, b1, v);
                        v = fmaf(w5, b2, v); v = fmaf(w6, c0, v);
                        v = fmaf(w7, c1, v); v = fmaf(w8, c2, v);
                        v = fminf(fmaxf(v, 0.f), 6.f);
                        const int gy = gy0 + i;
                        if (!((unsigned)gy < 256u) || !gxok) v = 0.f;  // keep padding zeros
                        out[k][r] = v;
                        a0 = b0; a1 = b1; a2 = b2;
                        b0 = c0; b1 = c1; b2 = c2;
                    }
                }
            }
        }
        __syncthreads();

        // ---- in-place writeback ----
        #pragma unroll
        for (int k = 0; k < 3; ++k) {
            const int cj = txt + 64 * k;
            const int j  = o + cj;
            if (cj < L) {
                #pragma unroll
                for (int r = 0; r < 24; ++r) {
                    if (rbase + r < L) buf[(r0 + r) * BSTR + j] = out[k][r];
                }
            }
        }
        __syncthreads();

        // ---- stream ys[s] interior (final 64x64) to gmem ----
        float* __restrict__ yd = g_ys + (size_t)s * NPIX + (size_t)b * 65536;
        for (int idx = threadIdx.x; idx < 4096; idx += 512) {
            int ii = idx >> 6, jj = idx & 63;
            yd[(gy0 + 64 + ii) * 256 + (gx0 + 64 + jj)] =
                buf[(64 + ii) * BSTR + (64 + jj)];
        }
        // next-stage compute only reads buf; its pre-writeback barrier orders
        // these LDS reads before any new writes -> no extra sync needed.
    }
}

// ---------------------------------------------------------------------------
// Kernel B: phase 2. out[pix] = sum_p cw[p]*clip(scale_p*(pw[p,:].ys[:,pix])+sh_p,0,6)
// Grid 2048, 256 threads, ~105 KB dyn smem (2 CTAs/SM).
// ---------------------------------------------------------------------------
__global__ void __launch_bounds__(256) phase2_kernel(const float* __restrict__ pw,
                                                     const float* __restrict__ gamma,
                                                     const float* __restrict__ beta,
                                                     const float* __restrict__ mean,
                                                     const float* __restrict__ var,
                                                     const float* __restrict__ cw,
                                                     float* __restrict__ out) {
    extern __shared__ float sm[];
    float* ytile = sm;                          // 64 x 256        (16384 f)
    u64*   pwd   = (u64*)(sm + 16384);          // pw dup pairs     (4096 u64)
    float* red   = sm + 16384 + 8192;           // reduction        (2048 f)
    float* sA    = red + 2048;                  // scale            (64 f)
    float* sB    = sA + 64;                     // shift            (64 f)
    float* sC    = sB + 64;                     // cw               (64 f)

    const int tid  = threadIdx.x;
    const int base = blockIdx.x * 256;

    // pw transposed + duplicated into f32x2 pairs: pwd[c*64+p] = (pw[p][c], pw[p][c])
    for (int i = tid; i < 4096; i += 256) {
        int c = i >> 6, p = i & 63;
        float v = pw[p * 64 + c];
        pwd[c * 64 + p] = f2pack(v, v);
    }
    if (tid < 64) {
        float sc = gamma[tid] * rsqrtf(var[tid] + 1e-5f);
        sA[tid] = sc;
        sB[tid] = beta[tid] - mean[tid] * sc;
        sC[tid] = cw[tid];
    }
    for (int c = 0; c < 64; ++c)
        ytile[c * 256 + tid] = g_ys[(size_t)c * NPIX + base + tid];
    __syncthreads();

    const int pg = tid >> 5;   // p-group 0..7  (8 p's each)
    const int qg = tid & 31;   // pixel-group 0..31 (8 px each)

    u64 acc[8][4];
    #pragma unroll
    for (int p = 0; p < 8; ++p)
        #pragma unroll
        for (int q = 0; q < 4; ++q) acc[p][q] = 0ull;

    #pragma unroll 4
    for (int c = 0; c < 64; ++c) {
        const u64* yp = (const u64*)(ytile + c * 256) + qg * 4;
        u64 y0 = yp[0], y1 = yp[1], y2 = yp[2], y3 = yp[3];
        const u64* wp = pwd + c * 64 + pg * 8;
        #pragma unroll
        for (int p = 0; p < 8; ++p) {
            u64 w = wp[p];
            acc[p][0] = f2fma(y0, w, acc[p][0]);
            acc[p][1] = f2fma(y1, w, acc[p][1]);
            acc[p][2] = f2fma(y2, w, acc[p][2]);
            acc[p][3] = f2fma(y3, w, acc[p][3]);
        }
    }

    // epilogue: BN + ReLU6 + cw-weighted partial sum over this thread's 8 p's
    float op[8];
    #pragma unroll
    for (int xq = 0; xq < 8; ++xq) op[xq] = 0.f;
    #pragma unroll
    for (int p = 0; p < 8; ++p) {
        const int gp = pg * 8 + p;
        const float sc = sA[gp], sh = sB[gp], wv = sC[gp];
        #pragma unroll
        for (int q = 0; q < 4; ++q) {
            float h0, h1; f2unpack(acc[p][q], h0, h1);
            float v0 = fminf(fmaxf(fmaf(h0, sc, sh), 0.f), 6.f);
            float v1 = fminf(fmaxf(fmaf(h1, sc, sh), 0.f), 6.f);
            op[2 * q    ] = fmaf(wv, v0, op[2 * q    ]);
            op[2 * q + 1] = fmaf(wv, v1, op[2 * q + 1]);
        }
    }
    #pragma unroll
    for (int xq = 0; xq < 8; ++xq) red[tid * 8 + xq] = op[xq];
    __syncthreads();

    // reduce over the 8 p-groups, write 256 outputs
    if (tid < 32) {
        #pragma unroll
        for (int xq = 0; xq < 8; ++xq) {
            float ssum = 0.f;
            #pragma unroll
            for (int g = 0; g < 8; ++g) ssum += red[(g * 32 + tid) * 8 + xq];
            out[base + tid * 8 + xq] = ssum;
        }
    }
}

// ---------------------------------------------------------------------------
extern "C" void kernel_launch(void* const* d_in, const int* in_sizes, int n_in,
                              void* d_out, int out_size) {
    const float* x     = (const float*)d_in[0];
    const float* dw    = (const float*)d_in[1];
    const float* pw    = (const float*)d_in[2];
    const float* gamma = (const float*)d_in[3];
    const float* beta  = (const float*)d_in[4];
    const float* mean  = (const float*)d_in[5];
    const float* var   = (const float*)d_in[6];
    const float* cw    = (const float*)d_in[7];
    float* out = (float*)d_out;

    const int SMEM_A = (BUF * BSTR + 576) * 4;          // 150528 B
    const int SMEM_B = (16384 + 8192 + 2048 + 192) * 4; // 107264 B

    cudaFuncSetAttribute(chain_kernel,  cudaFuncAttributeMaxDynamicSharedMemorySize, SMEM_A);
    cudaFuncSetAttribute(phase2_kernel, cudaFuncAttributeMaxDynamicSharedMemorySize, SMEM_B);

    chain_kernel<<<dim3(4, 4, 8), 512, SMEM_A>>>(x, dw);
    phase2_kernel<<<2048, 256, SMEM_B>>>(pw, gamma, beta, mean, var, cw, out);
}

// round 3
// speedup vs baseline: 2.0844x; 2.0844x over previous
#include <cuda_runtime.h>
#include <cstdint>

// ---------------------------------------------------------------------------
// SepConvLayer on GB300.
// Phase 1 (chain): 64 sequential 3x3 conv+ReLU6 stages, split into 4 launches
//   of 16 stages. Each launch: halo-16 recompute, 32x64 interior tiles,
//   ping-pong smem buffers, one barrier per stage. Group g>0 reads its input
//   (channel 16g-1) from g_ys written by the previous launch.
// Phase 2: per-pixel 64x64 matvec (f32x2 packed FMA) + BN + ReLU6 + 64->1.
// ---------------------------------------------------------------------------

#define NPIX (8 * 256 * 256)

// scratch: ys[c][b][h][w], 64 * 524288 floats = 134 MB
__device__ float g_ys[64ull * NPIX];

typedef unsigned long long u64;

__device__ __forceinline__ u64 f2fma(u64 a, u64 b, u64 c) {
    u64 d;
    asm("fma.rn.f32x2 %0, %1, %2, %3;" : "=l"(d) : "l"(a), "l"(b), "l"(c));
    return d;
}
__device__ __forceinline__ u64 f2pack(float x, float y) {
    u64 r; asm("mov.b64 %0, {%1, %2};" : "=l"(r) : "f"(x), "f"(y)); return r;
}
__device__ __forceinline__ void f2unpack(u64 v, float& x, float& y) {
    asm("mov.b64 {%0, %1}, %2;" : "=f"(x), "=f"(y) : "l"(v));
}

// ---------------------------------------------------------------------------
// Chain group kernel: 16 stages, halo 16. Interior 32 rows x 64 cols.
// Buffer: 64 rows x 96 cols (stride 97). Grid (4, 8, 8) = 256 CTAs, 256 thr.
// ---------------------------------------------------------------------------
#define GR 32
#define GC 64
#define HB 16
#define BR (GR + 2 * HB)   // 64
#define BC (GC + 2 * HB)   // 96
#define BST 97

__global__ void __launch_bounds__(256) chain16_kernel(const float* __restrict__ x,
                                                      const float* __restrict__ dw,
                                                      int g) {
    extern __shared__ float sm[];
    float* buf0 = sm;                       // BR*BST
    float* buf1 = sm + BR * BST;            // BR*BST
    float* wsh  = sm + 2 * BR * BST;        // 144

    const int b   = blockIdx.z;
    const int gy0 = blockIdx.y * GR;        // interior origin (global)
    const int gx0 = blockIdx.x * GC;

    // input image for this group: channel 0 of x, or ys[16g-1]
    const float* __restrict__ in = (g == 0)
        ? (x + (size_t)b * 64 * 65536)
        : (g_ys + (size_t)(16 * g - 1) * NPIX + (size_t)b * 65536);

    for (int i = threadIdx.x; i < 144; i += 256) wsh[i] = dw[g * 144 + i];

    // load 64x96 region, zero-fill outside image (SAME padding)
    for (int idx = threadIdx.x; idx < BR * BC; idx += 256) {
        int i = idx / BC, j = idx - i * BC;
        int gy = gy0 - HB + i, gx = gx0 - HB + j;
        float v = 0.f;
        if ((unsigned)gy < 256u && (unsigned)gx < 256u)
            v = __ldg(in + gy * 256 + gx);
        buf0[i * BST + j] = v;
    }
    __syncthreads();

    float* src = buf0;
    float* dst = buf1;
    const int cx = threadIdx.x & 127;   // column lane 0..127 (region <= 94 wide)
    const int ty = threadIdx.x >> 7;    // row band 0..1

    for (int s = 0; s < 16; ++s) {
        const float w0 = wsh[s * 9 + 0], w1 = wsh[s * 9 + 1], w2 = wsh[s * 9 + 2];
        const float w3 = wsh[s * 9 + 3], w4 = wsh[s * 9 + 4], w5 = wsh[s * 9 + 5];
        const float w6 = wsh[s * 9 + 6], w7 = wsh[s * 9 + 7], w8 = wsh[s * 9 + 8];

        const int o  = s + 1;
        const int Lr = BR - 2 - 2 * s;      // 62 - 2s
        const int Lc = BC - 2 - 2 * s;      // 94 - 2s
        const int rpb = (Lr + 1) >> 1;
        const int rbase = ty * rpb;
        int nrows = Lr - rbase; if (nrows > rpb) nrows = rpb;

        if (cx < Lc && nrows > 0) {
            const int j  = o + cx;
            const int i0 = o + rbase;
            const int gx = gx0 - HB + j;
            const bool gxok = (unsigned)gx < 256u;
            // prime vertical sliding window
            float a0 = src[(i0 - 1) * BST + j - 1];
            float a1 = src[(i0 - 1) * BST + j    ];
            float a2 = src[(i0 - 1) * BST + j + 1];
            float b0 = src[ i0      * BST + j - 1];
            float b1 = src[ i0      * BST + j    ];
            float b2 = src[ i0      * BST + j + 1];
            for (int r = 0; r < nrows; ++r) {
                const int i = i0 + r;
                float c0 = src[(i + 1) * BST + j - 1];
                float c1 = src[(i + 1) * BST + j    ];
                float c2 = src[(i + 1) * BST + j + 1];
                float v = w0 * a0;
                v = fmaf(w1, a1, v); v = fmaf(w2, a2, v);
                v = fmaf(w3, b0, v); v = fmaf(w4, b1, v);
                v = fmaf(w5, b2, v); v = fmaf(w6, c0, v);
                v = fmaf(w7, c1, v); v = fmaf(w8, c2, v);
                v = fminf(fmaxf(v, 0.f), 6.f);
                const int gy = gy0 - HB + i;
                if (!((unsigned)gy < 256u) || !gxok) v = 0.f;  // keep pad zeros
                dst[i * BST + j] = v;
                a0 = b0; a1 = b1; a2 = b2;
                b0 = c0; b1 = c1; b2 = c2;
            }
        }
        __syncthreads();

        // stream ys[16g+s] interior (32x64) to gmem from dst
        float* __restrict__ yo = g_ys + (size_t)(16 * g + s) * NPIX
                                      + (size_t)b * 65536;
        for (int k = threadIdx.x; k < GR * GC; k += 256) {
            int ii = k >> 6, jj = k & 63;
            yo[(gy0 + ii) * 256 + gx0 + jj] = dst[(HB + ii) * BST + HB + jj];
        }
        // next stage reads dst (ys store also only reads dst) and writes old
        // src, which nobody reads past the barrier above -> one BAR per stage.
        float* t = src; src = dst; dst = t;
    }
}

// ---------------------------------------------------------------------------
// Kernel B: phase 2. out[pix] = sum_p cw[p]*clip(scale_p*(pw[p,:].ys[:,pix])+sh_p,0,6)
// Grid 2048, 256 threads, ~105 KB dyn smem (2 CTAs/SM). LDS.128 everywhere.
// ---------------------------------------------------------------------------
__global__ void __launch_bounds__(256) phase2_kernel(const float* __restrict__ pw,
                                                     const float* __restrict__ gamma,
                                                     const float* __restrict__ beta,
                                                     const float* __restrict__ mean,
                                                     const float* __restrict__ var,
                                                     const float* __restrict__ cw,
                                                     float* __restrict__ out) {
    extern __shared__ float sm[];
    float* ytile = sm;                          // 64 x 256        (16384 f)
    u64*   pwd   = (u64*)(sm + 16384);          // pw dup pairs     (4096 u64)
    float* red   = sm + 16384 + 8192;           // reduction        (2048 f)
    float* sA    = red + 2048;                  // scale            (64 f)
    float* sB    = sA + 64;                     // shift            (64 f)
    float* sC    = sB + 64;                     // cw               (64 f)

    const int tid  = threadIdx.x;
    const int base = blockIdx.x * 256;

    // pw transposed + duplicated into f32x2 pairs: pwd[c*64+p] = (pw[p][c], pw[p][c])
    for (int i = tid; i < 4096; i += 256) {
        int c = i >> 6, p = i & 63;
        float v = pw[p * 64 + c];
        pwd[c * 64 + p] = f2pack(v, v);
    }
    if (tid < 64) {
        float sc = gamma[tid] * rsqrtf(var[tid] + 1e-5f);
        sA[tid] = sc;
        sB[tid] = beta[tid] - mean[tid] * sc;
        sC[tid] = cw[tid];
    }
    // stage y tile with float4 loads (coalesced LDG.128 / STS.128)
    {
        float4* yt4 = (float4*)ytile;
        for (int i = tid; i < 4096; i += 256) {
            int c = i >> 6, q = i & 63;
            yt4[c * 64 + q] =
                ((const float4*)(g_ys + (size_t)c * NPIX + base))[q];
        }
    }
    __syncthreads();

    const int pg = tid >> 5;   // p-group 0..7  (8 p's each)
    const int qg = tid & 31;   // pixel-group 0..31 (8 px each)

    u64 acc[8][4];
    #pragma unroll
    for (int p = 0; p < 8; ++p)
        #pragma unroll
        for (int q = 0; q < 4; ++q) acc[p][q] = 0ull;

    #pragma unroll 4
    for (int c = 0; c < 64; ++c) {
        const ulonglong2* yp = (const ulonglong2*)(ytile + c * 256 + qg * 8);
        ulonglong2 yA = yp[0];          // pixels 0,1 | 2,3
        ulonglong2 yB = yp[1];          // pixels 4,5 | 6,7
        const ulonglong2* wp = (const ulonglong2*)(pwd + c * 64 + pg * 8);
        ulonglong2 wA = wp[0], wB = wp[1], wC = wp[2], wD = wp[3];
        u64 w[8] = {wA.x, wA.y, wB.x, wB.y, wC.x, wC.y, wD.x, wD.y};
        #pragma unroll
        for (int p = 0; p < 8; ++p) {
            acc[p][0] = f2fma(yA.x, w[p], acc[p][0]);
            acc[p][1] = f2fma(yA.y, w[p], acc[p][1]);
            acc[p][2] = f2fma(yB.x, w[p], acc[p][2]);
            acc[p][3] = f2fma(yB.y, w[p], acc[p][3]);
        }
    }

    // epilogue: BN + ReLU6 + cw-weighted partial sum over this thread's 8 p's
    float op[8];
    #pragma unroll
    for (int xq = 0; xq < 8; ++xq) op[xq] = 0.f;
    #pragma unroll
    for (int p = 0; p < 8; ++p) {
        const int gp = pg * 8 + p;
        const float sc = sA[gp], sh = sB[gp], wv = sC[gp];
        #pragma unroll
        for (int q = 0; q < 4; ++q) {
            float h0, h1; f2unpack(acc[p][q], h0, h1);
            float v0 = fminf(fmaxf(fmaf(h0, sc, sh), 0.f), 6.f);
            float v1 = fminf(fmaxf(fmaf(h1, sc, sh), 0.f), 6.f);
            op[2 * q    ] = fmaf(wv, v0, op[2 * q    ]);
            op[2 * q + 1] = fmaf(wv, v1, op[2 * q + 1]);
        }
    }
    #pragma unroll
    for (int xq = 0; xq < 8; ++xq) red[tid * 8 + xq] = op[xq];
    __syncthreads();

    // reduce over the 8 p-groups, write 256 outputs
    if (tid < 32) {
        #pragma unroll
        for (int xq = 0; xq < 8; ++xq) {
            float ssum = 0.f;
            #pragma unroll
            for (int g = 0; g < 8; ++g) ssum += red[(g * 32 + tid) * 8 + xq];
            out[base + tid * 8 + xq] = ssum;
        }
    }
}

// ---------------------------------------------------------------------------
extern "C" void kernel_launch(void* const* d_in, const int* in_sizes, int n_in,
                              void* d_out, int out_size) {
    const float* x     = (const float*)d_in[0];
    const float* dw    = (const float*)d_in[1];
    const float* pw    = (const float*)d_in[2];
    const float* gamma = (const float*)d_in[3];
    const float* beta  = (const float*)d_in[4];
    const float* mean  = (const float*)d_in[5];
    const float* var   = (const float*)d_in[6];
    const float* cw    = (const float*)d_in[7];
    float* out = (float*)d_out;

    const int SMEM_A = (2 * BR * BST + 144) * 4;        // ~50.2 KB
    const int SMEM_B = (16384 + 8192 + 2048 + 192) * 4; // 107264 B

    cudaFuncSetAttribute(chain16_kernel, cudaFuncAttributeMaxDynamicSharedMemorySize, SMEM_A);
    cudaFuncSetAttribute(phase2_kernel,  cudaFuncAttributeMaxDynamicSharedMemorySize, SMEM_B);

    for (int g = 0; g < 4; ++g)
        chain16_kernel<<<dim3(4, 8, 8), 256, SMEM_A>>>(x, dw, g);
    phase2_kernel<<<2048, 256, SMEM_B>>>(pw, gamma, beta, mean, var, cw, out);
}

// round 8
// speedup vs baseline: 2.9007x; 1.3916x over previous
#include <cuda_runtime.h>
#include <cuda_bf16.h>
#include <cstdint>

// ---------------------------------------------------------------------------
// SepConvLayer on GB300 (sm_103 baseline-PTX only: mma.sync, ldmatrix).
// Phase 1: 64 sequential 3x3 conv+ReLU6 stages, 4 launches of 16 stages
//          (halo-16 recompute, ping-pong smem, 512 threads/CTA).
// Phase 2: bf16 split GEMM via mma.sync.m16n8k16 (hi/lo, 3 passes, fp32 acc)
//          + BN + ReLU6 + cw reduction epilogue.
// ---------------------------------------------------------------------------

#define NPIX (8 * 256 * 256)
__device__ float g_ys[64ull * NPIX];   // ys[c][b][h][w], fp32, 134 MB

__device__ __forceinline__ uint32_t smem_u32(const void* p) {
    uint32_t a;
    asm("{ .reg .u64 t; cvta.to.shared.u64 t, %1; cvt.u32.u64 %0, t; }"
        : "=r"(a) : "l"(p));
    return a;
}
__device__ __forceinline__ void ldmatrix_x4(uint32_t* r, uint32_t addr) {
    asm volatile("ldmatrix.sync.aligned.m8n8.x4.shared.b16 {%0,%1,%2,%3}, [%4];"
                 : "=r"(r[0]), "=r"(r[1]), "=r"(r[2]), "=r"(r[3]) : "r"(addr));
}
__device__ __forceinline__ void ldmatrix_x2t(uint32_t& r0, uint32_t& r1, uint32_t addr) {
    asm volatile("ldmatrix.sync.aligned.m8n8.x2.trans.shared.b16 {%0,%1}, [%2];"
                 : "=r"(r0), "=r"(r1) : "r"(addr));
}
__device__ __forceinline__ void mma_bf16(float* d, const uint32_t* a,
                                         uint32_t b0, uint32_t b1) {
    asm volatile("mma.sync.aligned.m16n8k16.row.col.f32.bf16.bf16.f32 "
                 "{%0,%1,%2,%3}, {%4,%5,%6,%7}, {%8,%9}, {%0,%1,%2,%3};"
                 : "+f"(d[0]), "+f"(d[1]), "+f"(d[2]), "+f"(d[3])
                 : "r"(a[0]), "r"(a[1]), "r"(a[2]), "r"(a[3]), "r"(b0), "r"(b1));
}

// ---------------------------------------------------------------------------
// Chain group kernel: 16 stages, halo 16. Interior 32x64. 512 threads.
// ---------------------------------------------------------------------------
#define GR 32
#define GC 64
#define HB 16
#define BR (GR + 2 * HB)   // 64
#define BC (GC + 2 * HB)   // 96
#define BST 97

__global__ void __launch_bounds__(512) chain16_kernel(const float* __restrict__ x,
                                                      const float* __restrict__ dw,
                                                      int g) {
    extern __shared__ float sm[];
    float* buf0 = sm;
    float* buf1 = sm + BR * BST;
    float* wsh  = sm + 2 * BR * BST;

    const int b   = blockIdx.z;
    const int gy0 = blockIdx.y * GR;
    const int gx0 = blockIdx.x * GC;

    const float* __restrict__ in = (g == 0)
        ? (x + (size_t)b * 64 * 65536)
        : (g_ys + (size_t)(16 * g - 1) * NPIX + (size_t)b * 65536);

    for (int i = threadIdx.x; i < 144; i += 512) wsh[i] = dw[g * 144 + i];

    for (int idx = threadIdx.x; idx < BR * BC; idx += 512) {
        int i = idx / BC, j = idx - i * BC;
        int gy = gy0 - HB + i, gx = gx0 - HB + j;
        float v = 0.f;
        if ((unsigned)gy < 256u && (unsigned)gx < 256u)
            v = __ldg(in + gy * 256 + gx);
        buf0[i * BST + j] = v;
    }
    __syncthreads();

    float* src = buf0;
    float* dst = buf1;
    const int cx = threadIdx.x & 127;   // 0..127 (region <= 94 wide)
    const int ty = threadIdx.x >> 7;    // 0..3

    for (int s = 0; s < 16; ++s) {
        const float w0 = wsh[s * 9 + 0], w1 = wsh[s * 9 + 1], w2 = wsh[s * 9 + 2];
        const float w3 = wsh[s * 9 + 3], w4 = wsh[s * 9 + 4], w5 = wsh[s * 9 + 5];
        const float w6 = wsh[s * 9 + 6], w7 = wsh[s * 9 + 7], w8 = wsh[s * 9 + 8];

        const int o  = s + 1;
        const int Lr = BR - 2 - 2 * s;
        const int Lc = BC - 2 - 2 * s;
        const int rpb = (Lr + 3) >> 2;
        const int rbase = ty * rpb;
        int nrows = Lr - rbase; if (nrows > rpb) nrows = rpb;

        if (cx < Lc && nrows > 0) {
            const int j  = o + cx;
            const int i0 = o + rbase;
            const int gx = gx0 - HB + j;
            const bool gxok = (unsigned)gx < 256u;
            float a0 = src[(i0 - 1) * BST + j - 1];
            float a1 = src[(i0 - 1) * BST + j    ];
            float a2 = src[(i0 - 1) * BST + j + 1];
            float b0 = src[ i0      * BST + j - 1];
            float b1 = src[ i0      * BST + j    ];
            float b2 = src[ i0      * BST + j + 1];
            for (int r = 0; r < nrows; ++r) {
                const int i = i0 + r;
                float c0 = src[(i + 1) * BST + j - 1];
                float c1 = src[(i + 1) * BST + j    ];
                float c2 = src[(i + 1) * BST + j + 1];
                float v = w0 * a0;
                v = fmaf(w1, a1, v); v = fmaf(w2, a2, v);
                v = fmaf(w3, b0, v); v = fmaf(w4, b1, v);
                v = fmaf(w5, b2, v); v = fmaf(w6, c0, v);
                v = fmaf(w7, c1, v); v = fmaf(w8, c2, v);
                v = fminf(fmaxf(v, 0.f), 6.f);
                const int gy = gy0 - HB + i;
                if (!((unsigned)gy < 256u) || !gxok) v = 0.f;
                dst[i * BST + j] = v;
                a0 = b0; a1 = b1; a2 = b2;
                b0 = c0; b1 = c1; b2 = c2;
            }
        }
        __syncthreads();

        float* __restrict__ yo = g_ys + (size_t)(16 * g + s) * NPIX
                                      + (size_t)b * 65536;
        for (int k = threadIdx.x; k < GR * GC; k += 512) {
            int ii = k >> 6, jj = k & 63;
            yo[(gy0 + ii) * 256 + gx0 + jj] = dst[(HB + ii) * BST + HB + jj];
        }
        float* t = src; src = dst; dst = t;
    }
}

// ---------------------------------------------------------------------------
// Phase-2 GEMM (mma.sync bf16 split). Per CTA: 256 px.
// A = pw [64p x 64c] hi/lo, row stride 144B. B = y [64c x 256px] hi/lo,
// row stride 528B. 8 warps: wr = wid&1 (32 p), wc = wid>>1 (64 px).
// ---------------------------------------------------------------------------
#define ASTR 144            // bytes per A row (64c*2 + 16 pad)
#define BSTR 528            // bytes per B row (256px*2 + 16 pad)
#define OFF_AH 0
#define OFF_AL (OFF_AH + 64 * ASTR)     //  9216
#define OFF_BH (OFF_AL + 64 * ASTR)     // 18432
#define OFF_BL (OFF_BH + 64 * BSTR)     // 52224
#define OFF_RED (OFF_BL + 64 * BSTR)    // 86016
#define SMEM_G (OFF_RED + 512 * 4)      // 88064

__global__ void __launch_bounds__(256) gemm_kernel(const float* __restrict__ pw,
                                                   const float* __restrict__ gamma,
                                                   const float* __restrict__ beta,
                                                   const float* __restrict__ mean,
                                                   const float* __restrict__ var,
                                                   const float* __restrict__ cw,
                                                   float* __restrict__ out) {
    extern __shared__ char smc[];
    const uint32_t smb = smem_u32(smc);
    const int tid = threadIdx.x, wid = tid >> 5, lane = tid & 31;
    const size_t base = (size_t)blockIdx.x * 256;

    // ---- stage A = pw hi/lo ----
    #pragma unroll
    for (int it = 0; it < 8; ++it) {
        int idx = it * 256 + tid;          // 0..2047
        int p = idx >> 5, c2 = (idx & 31) * 2;
        float2 v = *(const float2*)(pw + p * 64 + c2);
        __nv_bfloat16 h0 = __float2bfloat16(v.x);
        __nv_bfloat16 l0 = __float2bfloat16(v.x - __bfloat162float(h0));
        __nv_bfloat16 h1 = __float2bfloat16(v.y);
        __nv_bfloat16 l1 = __float2bfloat16(v.y - __bfloat162float(h1));
        *(__nv_bfloat162*)(smc + OFF_AH + p * ASTR + c2 * 2) = __nv_bfloat162(h0, h1);
        *(__nv_bfloat162*)(smc + OFF_AL + p * ASTR + c2 * 2) = __nv_bfloat162(l0, l1);
    }
    // ---- stage B = y hi/lo ----
    #pragma unroll
    for (int it = 0; it < 32; ++it) {
        int idx = it * 256 + tid;          // 0..8191
        int c = idx >> 7, px2 = (idx & 127) * 2;
        float2 v = *(const float2*)(g_ys + (size_t)c * NPIX + base + px2);
        __nv_bfloat16 h0 = __float2bfloat16(v.x);
        __nv_bfloat16 l0 = __float2bfloat16(v.x - __bfloat162float(h0));
        __nv_bfloat16 h1 = __float2bfloat16(v.y);
        __nv_bfloat16 l1 = __float2bfloat16(v.y - __bfloat162float(h1));
        *(__nv_bfloat162*)(smc + OFF_BH + c * BSTR + px2 * 2) = __nv_bfloat162(h0, h1);
        *(__nv_bfloat162*)(smc + OFF_BL + c * BSTR + px2 * 2) = __nv_bfloat162(l0, l1);
    }
    __syncthreads();

    const int wr = wid & 1;     // p-block (32 p)
    const int wc = wid >> 1;    // px-block (64 px)

    float d[2][8][4];
    #pragma unroll
    for (int mt = 0; mt < 2; ++mt)
        #pragma unroll
        for (int nt = 0; nt < 8; ++nt)
            #pragma unroll
            for (int q = 0; q < 4; ++q) d[mt][nt][q] = 0.f;

    // ldmatrix base addresses
    const uint32_t aRow = wr * 32 + (lane & 15);
    const uint32_t aOff = (lane >> 4) * 16;              // k-halves
    const uint32_t aH = smb + OFF_AH + aRow * ASTR + aOff;
    const uint32_t aL = smb + OFF_AL + aRow * ASTR + aOff;
    const uint32_t bRow = (lane & 15);
    const uint32_t bH = smb + OFF_BH + bRow * BSTR + wc * 128;
    const uint32_t bL = smb + OFF_BL + bRow * BSTR + wc * 128;

    #pragma unroll
    for (int ks = 0; ks < 4; ++ks) {
        uint32_t ah[2][4], al[2][4];
        ldmatrix_x4(ah[0], aH + ks * 32);
        ldmatrix_x4(ah[1], aH + 16 * ASTR + ks * 32);
        ldmatrix_x4(al[0], aL + ks * 32);
        ldmatrix_x4(al[1], aL + 16 * ASTR + ks * 32);
        #pragma unroll
        for (int nt = 0; nt < 8; ++nt) {
            uint32_t bh0, bh1, bl0, bl1;
            ldmatrix_x2t(bh0, bh1, bH + ks * 16 * BSTR + nt * 16);
            ldmatrix_x2t(bl0, bl1, bL + ks * 16 * BSTR + nt * 16);
            #pragma unroll
            for (int mt = 0; mt < 2; ++mt) {
                mma_bf16(d[mt][nt], ah[mt], bh0, bh1);   // hi*hi
                mma_bf16(d[mt][nt], ah[mt], bl0, bl1);   // hi*lo
                mma_bf16(d[mt][nt], al[mt], bh0, bh1);   // lo*hi
            }
        }
    }

    // ---- epilogue: BN + ReLU6 + cw, reduce over p ----
    float sc[4], sh[4], wv[4];
    {
        const int q0 = wr * 32 + (lane >> 2);
        #pragma unroll
        for (int j = 0; j < 4; ++j) {        // p = q0 + 8*j
            int p = q0 + 8 * j;
            float s = gamma[p] * rsqrtf(var[p] + 1e-5f);
            sc[j] = s; sh[j] = beta[p] - mean[p] * s; wv[j] = cw[p];
        }
    }
    float* red = (float*)(smc + OFF_RED);
    #pragma unroll
    for (int nt = 0; nt < 8; ++nt) {
        float v0 = 0.f, v1 = 0.f;
        #pragma unroll
        for (int mt = 0; mt < 2; ++mt) {
            #pragma unroll
            for (int h = 0; h < 2; ++h) {    // rows g, g+8
                const int j = mt * 2 + h;
                float u0 = fminf(fmaxf(fmaf(sc[j], d[mt][nt][h * 2    ], sh[j]), 0.f), 6.f);
                float u1 = fminf(fmaxf(fmaf(sc[j], d[mt][nt][h * 2 + 1], sh[j]), 0.f), 6.f);
                v0 = fmaf(wv[j], u0, v0);
                v1 = fmaf(wv[j], u1, v1);
            }
        }
        #pragma unroll
        for (int off = 4; off < 32; off <<= 1) {
            v0 += __shfl_xor_sync(0xffffffffu, v0, off);
            v1 += __shfl_xor_sync(0xffffffffu, v1, off);
        }
        if (lane < 4)
            *(float2*)(red + wr * 256 + wc * 64 + nt * 8 + lane * 2) =
                make_float2(v0, v1);
    }
    __syncthreads();
    out[base + tid] = red[tid] + red[256 + tid];
}

// ---------------------------------------------------------------------------
extern "C" void kernel_launch(void* const* d_in, const int* in_sizes, int n_in,
                              void* d_out, int out_size) {
    const float* x     = (const float*)d_in[0];
    const float* dw    = (const float*)d_in[1];
    const float* pw    = (const float*)d_in[2];
    const float* gamma = (const float*)d_in[3];
    const float* beta  = (const float*)d_in[4];
    const float* mean  = (const float*)d_in[5];
    const float* var   = (const float*)d_in[6];
    const float* cw    = (const float*)d_in[7];
    float* out = (float*)d_out;

    const int SMEM_A = (2 * BR * BST + 144) * 4;

    cudaFuncSetAttribute(chain16_kernel, cudaFuncAttributeMaxDynamicSharedMemorySize, SMEM_A);
    cudaFuncSetAttribute(gemm_kernel,    cudaFuncAttributeMaxDynamicSharedMemorySize, SMEM_G);

    for (int g = 0; g < 4; ++g)
        chain16_kernel<<<dim3(4, 8, 8), 512, SMEM_A>>>(x, dw, g);
    gemm_kernel<<<2048, 256, SMEM_G>>>(pw, gamma, beta, mean, var, cw, out);
}

// round 9
// speedup vs baseline: 3.3819x; 1.1659x over previous
#include <cuda_runtime.h>
#include <cuda_bf16.h>
#include <cstdint>

// ---------------------------------------------------------------------------
// SepConvLayer on GB300 (sm_103 baseline PTX: mma.sync / ldmatrix / cp.async).
// Phase 1: 64 conv+ReLU6 stages, 8 launches x 8 stages, halo-8 recompute,
//          fixed 80x80 compute region (fully unrolled), 64x64 interior,
//          128 CTAs (one per SM, no wave imbalance), 640 threads.
//          ys written as split bf16 hi/lo planes; fp32 seed for next launch.
// Phase 2: bf16 split GEMM via mma.sync.m16n8k16 (hi/lo, 3 passes, fp32 acc),
//          B staged with cp.async, + BN + ReLU6 + cw reduction epilogue.
// ---------------------------------------------------------------------------

#define NPIX (8 * 256 * 256)
__device__ __nv_bfloat16 g_ys_hi[64ull * NPIX];   // 64 MB
__device__ __nv_bfloat16 g_ys_lo[64ull * NPIX];   // 64 MB
__device__ float        g_seed[NPIX];             // 2 MB (inter-launch seed)

__device__ __forceinline__ uint32_t smem_u32(const void* p) {
    uint32_t a;
    asm("{ .reg .u64 t; cvta.to.shared.u64 t, %1; cvt.u32.u64 %0, t; }"
        : "=r"(a) : "l"(p));
    return a;
}
__device__ __forceinline__ void ldmatrix_x4(uint32_t* r, uint32_t addr) {
    asm volatile("ldmatrix.sync.aligned.m8n8.x4.shared.b16 {%0,%1,%2,%3}, [%4];"
                 : "=r"(r[0]), "=r"(r[1]), "=r"(r[2]), "=r"(r[3]) : "r"(addr));
}
__device__ __forceinline__ void ldmatrix_x2t(uint32_t& r0, uint32_t& r1, uint32_t addr) {
    asm volatile("ldmatrix.sync.aligned.m8n8.x2.trans.shared.b16 {%0,%1}, [%2];"
                 : "=r"(r0), "=r"(r1) : "r"(addr));
}
__device__ __forceinline__ void mma_bf16(float* d, const uint32_t* a,
                                         uint32_t b0, uint32_t b1) {
    asm volatile("mma.sync.aligned.m16n8k16.row.col.f32.bf16.bf16.f32 "
                 "{%0,%1,%2,%3}, {%4,%5,%6,%7}, {%8,%9}, {%0,%1,%2,%3};"
                 : "+f"(d[0]), "+f"(d[1]), "+f"(d[2]), "+f"(d[3])
                 : "r"(a[0]), "r"(a[1]), "r"(a[2]), "r"(a[3]), "r"(b0), "r"(b1));
}
__device__ __forceinline__ void cp_async16(uint32_t sdst, const void* gsrc) {
    asm volatile("cp.async.cg.shared.global [%0], [%1], 16;"
                 :: "r"(sdst), "l"(gsrc) : "memory");
}

// ---------------------------------------------------------------------------
// Chain kernel: 8 stages, halo 8 (+1 garbage ring). Interior 64x64.
// Buffer 82 rows x 84 cols (stride 84, even for LDS.64). Fixed region:
// rows 1..80, cols 1..80. 640 threads = 16 bands x 40 col-units (2 cols each).
// Grid (4,4,8) = 128 CTAs.
// ---------------------------------------------------------------------------
#define CBR 82
#define CBC 82
#define CBS 84

__global__ void __launch_bounds__(640) chain8_kernel(const float* __restrict__ x,
                                                     const float* __restrict__ dw,
                                                     int g) {
    extern __shared__ float sm[];
    float* buf0 = sm;                    // CBR*CBS
    float* buf1 = sm + CBR * CBS;
    float* wsh  = sm + 2 * CBR * CBS;    // 72

    const int b   = blockIdx.z;
    const int gy0 = blockIdx.y * 64;
    const int gx0 = blockIdx.x * 64;

    const float* __restrict__ in = (g == 0)
        ? (x + (size_t)b * 64 * 65536)
        : (g_seed + (size_t)b * 65536);

    for (int i = threadIdx.x; i < 72; i += 640) wsh[i] = dw[g * 72 + i];

    // load 82x82 region (interior + 8 halo + 1 garbage ring), zero OOB
    for (int idx = threadIdx.x; idx < CBR * CBC; idx += 640) {
        int i = idx / CBC, j = idx - i * CBC;
        int gy = gy0 + i - 9, gx = gx0 + j - 9;
        float v = 0.f;
        if ((unsigned)gy < 256u && (unsigned)gx < 256u)
            v = __ldg(in + gy * 256 + gx);
        buf0[i * CBS + j] = v;
    }
    __syncthreads();

    const int cu   = (int)threadIdx.x % 40;   // col unit (2 cols)
    const int band = (int)threadIdx.x / 40;   // 0..15
    const int j    = 1 + 2 * cu;              // odd col -> (j-1,j),(j+1,j+2) aligned
    const int i0   = 1 + band * 5;
    const bool okA = (unsigned)(gx0 + j - 9)  < 256u;
    const bool okB = (unsigned)(gx0 + j - 8)  < 256u;

    float* src = buf0;
    float* dst = buf1;

    #pragma unroll
    for (int s = 0; s < 8; ++s) {
        const float w0 = wsh[s * 9 + 0], w1 = wsh[s * 9 + 1], w2 = wsh[s * 9 + 2];
        const float w3 = wsh[s * 9 + 3], w4 = wsh[s * 9 + 4], w5 = wsh[s * 9 + 5];
        const float w6 = wsh[s * 9 + 6], w7 = wsh[s * 9 + 7], w8 = wsh[s * 9 + 8];

        // prime 2-row window (4 cols per row as two float2)
        float2 pA = *(const float2*)&src[(i0 - 1) * CBS + j - 1];
        float2 pB = *(const float2*)&src[(i0 - 1) * CBS + j + 1];
        float2 qA = *(const float2*)&src[(i0    ) * CBS + j - 1];
        float2 qB = *(const float2*)&src[(i0    ) * CBS + j + 1];

        #pragma unroll
        for (int r = 0; r < 5; ++r) {
            const int i = i0 + r;
            float2 rA = *(const float2*)&src[(i + 1) * CBS + j - 1];
            float2 rB = *(const float2*)&src[(i + 1) * CBS + j + 1];

            float v0 = w0 * pA.x;
            v0 = fmaf(w1, pA.y, v0); v0 = fmaf(w2, pB.x, v0);
            v0 = fmaf(w3, qA.x, v0); v0 = fmaf(w4, qA.y, v0);
            v0 = fmaf(w5, qB.x, v0); v0 = fmaf(w6, rA.x, v0);
            v0 = fmaf(w7, rA.y, v0); v0 = fmaf(w8, rB.x, v0);

            float v1 = w0 * pA.y;
            v1 = fmaf(w1, pB.x, v1); v1 = fmaf(w2, pB.y, v1);
            v1 = fmaf(w3, qA.y, v1); v1 = fmaf(w4, qB.x, v1);
            v1 = fmaf(w5, qB.y, v1); v1 = fmaf(w6, rA.y, v1);
            v1 = fmaf(w7, rB.x, v1); v1 = fmaf(w8, rB.y, v1);

            v0 = fminf(fmaxf(v0, 0.f), 6.f);
            v1 = fminf(fmaxf(v1, 0.f), 6.f);

            const bool gyok = (unsigned)(gy0 + i - 9) < 256u;
            if (!(gyok && okA)) v0 = 0.f;       // SAME-padding zeros
            if (!(gyok && okB)) v1 = 0.f;

            dst[i * CBS + j    ] = v0;
            dst[i * CBS + j + 1] = v1;

            pA = qA; pB = qB; qA = rA; qB = rB;
        }
        __syncthreads();

        // stream interior (64x64) of stage output: bf16 hi/lo planes (+ seed)
        const int ch = 8 * g + s;
        __nv_bfloat16* __restrict__ yh = g_ys_hi + (size_t)ch * NPIX + (size_t)b * 65536;
        __nv_bfloat16* __restrict__ yl = g_ys_lo + (size_t)ch * NPIX + (size_t)b * 65536;
        for (int k = threadIdx.x; k < 4096; k += 640) {
            int ii = k >> 6, jj = k & 63;
            float v = dst[(9 + ii) * CBS + 9 + jj];
            __nv_bfloat16 h = __float2bfloat16(v);
            __nv_bfloat16 l = __float2bfloat16(v - __bfloat162float(h));
            size_t go = (size_t)(gy0 + ii) * 256 + gx0 + jj;
            yh[go] = h;
            yl[go] = l;
            if (s == 7)
                g_seed[(size_t)b * 65536 + go] = v;
        }
        float* t = src; src = dst; dst = t;
    }
}

// ---------------------------------------------------------------------------
// Phase-2 GEMM (mma.sync bf16 split). Per CTA: 256 px.
// A = pw [64p x 64c] hi/lo (fp32->split in-kernel), row stride 144B.
// B = y hi/lo planes staged by cp.async, row stride 528B.
// 8 warps: wr = wid&1 (32 p), wc = wid>>1 (64 px).
// ---------------------------------------------------------------------------
#define ASTR 144
#define BSTR 528
#define OFF_AH 0
#define OFF_AL (OFF_AH + 64 * ASTR)     //  9216
#define OFF_BH (OFF_AL + 64 * ASTR)     // 18432
#define OFF_BL (OFF_BH + 64 * BSTR)     // 52224
#define OFF_RED (OFF_BL + 64 * BSTR)    // 86016
#define SMEM_G (OFF_RED + 512 * 4)      // 88064

__global__ void __launch_bounds__(256) gemm_kernel(const float* __restrict__ pw,
                                                   const float* __restrict__ gamma,
                                                   const float* __restrict__ beta,
                                                   const float* __restrict__ mean,
                                                   const float* __restrict__ var,
                                                   const float* __restrict__ cw,
                                                   float* __restrict__ out) {
    extern __shared__ char smc[];
    const uint32_t smb = smem_u32(smc);
    const int tid = threadIdx.x, wid = tid >> 5, lane = tid & 31;
    const size_t base = (size_t)blockIdx.x * 256;

    // ---- issue cp.async for B (64 rows x 32 x 16B chunks, 2 planes) ----
    #pragma unroll
    for (int it = 0; it < 8; ++it) {                // hi plane
        int idx = it * 256 + tid;                   // 0..2047
        int c = idx >> 5, chn = idx & 31;
        const char* gsrc = (const char*)(g_ys_hi + (size_t)c * NPIX + base) + chn * 16;
        cp_async16(smb + OFF_BH + c * BSTR + chn * 16, gsrc);
    }
    #pragma unroll
    for (int it = 0; it < 8; ++it) {                // lo plane
        int idx = it * 256 + tid;
        int c = idx >> 5, chn = idx & 31;
        const char* gsrc = (const char*)(g_ys_lo + (size_t)c * NPIX + base) + chn * 16;
        cp_async16(smb + OFF_BL + c * BSTR + chn * 16, gsrc);
    }
    asm volatile("cp.async.commit_group;" ::: "memory");

    // ---- stage A = pw hi/lo (overlaps cp.async) ----
    #pragma unroll
    for (int it = 0; it < 8; ++it) {
        int idx = it * 256 + tid;          // 0..2047
        int p = idx >> 5, c2 = (idx & 31) * 2;
        float2 v = *(const float2*)(pw + p * 64 + c2);
        __nv_bfloat16 h0 = __float2bfloat16(v.x);
        __nv_bfloat16 l0 = __float2bfloat16(v.x - __bfloat162float(h0));
        __nv_bfloat16 h1 = __float2bfloat16(v.y);
        __nv_bfloat16 l1 = __float2bfloat16(v.y - __bfloat162float(h1));
        *(__nv_bfloat162*)(smc + OFF_AH + p * ASTR + c2 * 2) = __nv_bfloat162(h0, h1);
        *(__nv_bfloat162*)(smc + OFF_AL + p * ASTR + c2 * 2) = __nv_bfloat162(l0, l1);
    }
    asm volatile("cp.async.wait_group 0;" ::: "memory");
    __syncthreads();

    const int wr = wid & 1;     // p-block (32 p)
    const int wc = wid >> 1;    // px-block (64 px)

    float d[2][8][4];
    #pragma unroll
    for (int mt = 0; mt < 2; ++mt)
        #pragma unroll
        for (int nt = 0; nt < 8; ++nt)
            #pragma unroll
            for (int q = 0; q < 4; ++q) d[mt][nt][q] = 0.f;

    const uint32_t aRow = wr * 32 + (lane & 15);
    const uint32_t aOff = (lane >> 4) * 16;
    const uint32_t aH = smb + OFF_AH + aRow * ASTR + aOff;
    const uint32_t aL = smb + OFF_AL + aRow * ASTR + aOff;
    const uint32_t bRow = (lane & 15);
    const uint32_t bH = smb + OFF_BH + bRow * BSTR + wc * 128;
    const uint32_t bL = smb + OFF_BL + bRow * BSTR + wc * 128;

    #pragma unroll
    for (int ks = 0; ks < 4; ++ks) {
        uint32_t ah[2][4], al[2][4];
        ldmatrix_x4(ah[0], aH + ks * 32);
        ldmatrix_x4(ah[1], aH + 16 * ASTR + ks * 32);
        ldmatrix_x4(al[0], aL + ks * 32);
        ldmatrix_x4(al[1], aL + 16 * ASTR + ks * 32);
        #pragma unroll
        for (int nt = 0; nt < 8; ++nt) {
            uint32_t bh0, bh1, bl0, bl1;
            ldmatrix_x2t(bh0, bh1, bH + ks * 16 * BSTR + nt * 16);
            ldmatrix_x2t(bl0, bl1, bL + ks * 16 * BSTR + nt * 16);
            #pragma unroll
            for (int mt = 0; mt < 2; ++mt) {
                mma_bf16(d[mt][nt], ah[mt], bh0, bh1);   // hi*hi
                mma_bf16(d[mt][nt], ah[mt], bl0, bl1);   // hi*lo
                mma_bf16(d[mt][nt], al[mt], bh0, bh1);   // lo*hi
            }
        }
    }

    // ---- epilogue: BN + ReLU6 + cw, reduce over p ----
    float sc[4], sh[4], wv[4];
    {
        const int q0 = wr * 32 + (lane >> 2);
        #pragma unroll
        for (int jj = 0; jj < 4; ++jj) {
            int p = q0 + 8 * jj;
            float s = gamma[p] * rsqrtf(var[p] + 1e-5f);
            sc[jj] = s; sh[jj] = beta[p] - mean[p] * s; wv[jj] = cw[p];
        }
    }
    float* red = (float*)(smc + OFF_RED);
    #pragma unroll
    for (int nt = 0; nt < 8; ++nt) {
        float v0 = 0.f, v1 = 0.f;
        #pragma unroll
        for (int mt = 0; mt < 2; ++mt) {
            #pragma unroll
            for (int h = 0; h < 2; ++h) {
                const int jj = mt * 2 + h;
                float u0 = fminf(fmaxf(fmaf(sc[jj], d[mt][nt][h * 2    ], sh[jj]), 0.f), 6.f);
                float u1 = fminf(fmaxf(fmaf(sc[jj], d[mt][nt][h * 2 + 1], sh[jj]), 0.f), 6.f);
                v0 = fmaf(wv[jj], u0, v0);
                v1 = fmaf(wv[jj], u1, v1);
            }
        }
        #pragma unroll
        for (int off = 4; off < 32; off <<= 1) {
            v0 += __shfl_xor_sync(0xffffffffu, v0, off);
            v1 += __shfl_xor_sync(0xffffffffu, v1, off);
        }
        if (lane < 4)
            *(float2*)(red + wr * 256 + wc * 64 + nt * 8 + lane * 2) =
                make_float2(v0, v1);
    }
    __syncthreads();
    out[base + tid] = red[tid] + red[256 + tid];
}

// ---------------------------------------------------------------------------
extern "C" void kernel_launch(void* const* d_in, const int* in_sizes, int n_in,
                              void* d_out, int out_size) {
    const float* x     = (const float*)d_in[0];
    const float* dw    = (const float*)d_in[1];
    const float* pw    = (const float*)d_in[2];
    const float* gamma = (const float*)d_in[3];
    const float* beta  = (const float*)d_in[4];
    const float* mean  = (const float*)d_in[5];
    const float* var   = (const float*)d_in[6];
    const float* cw    = (const float*)d_in[7];
    float* out = (float*)d_out;

    const int SMEM_C = (2 * CBR * CBS + 72) * 4;   // ~55.4 KB

    cudaFuncSetAttribute(chain8_kernel, cudaFuncAttributeMaxDynamicSharedMemorySize, SMEM_C);
    cudaFuncSetAttribute(gemm_kernel,   cudaFuncAttributeMaxDynamicSharedMemorySize, SMEM_G);

    for (int g = 0; g < 8; ++g)
        chain8_kernel<<<dim3(4, 4, 8), 640, SMEM_C>>>(x, dw, g);
    gemm_kernel<<<2048, 256, SMEM_G>>>(pw, gamma, beta, mean, var, cw, out);
}